// round 6
// baseline (speedup 1.0000x reference)
#include <cuda_runtime.h>

// Problem constants (from reference)
#define BB      16      // batch
#define SS      256     // SU == SV
#define DEG     3       // P == Q
#define KLEN    132     // M + P + 2 == N + Q + 2
#define NCTRL   128     // M+1 == N+1
#define MAXSPAN 127     // M == N
#define NSPAN   (KLEN - 2*DEG)   // 126 candidate spans

// Precomputed per-(b, sample): basis weights (4) and span index, for u and v.
__device__ float4 g_Nu[BB][SS];
__device__ float4 g_Nv[BB][SS];
__device__ int    g_us[BB][SS];
__device__ int    g_vs[BB][SS];

// Find span (exact argmin-first-occurrence replica) + Cox-de Boor basis.
__device__ __forceinline__ void span_basis(const float* __restrict__ Kn, float t,
                                           int& span_out, float4& N_out) {
    // _find_spans: masked = where(d > EPS, d, 1.0); argmin (first occurrence)
    float best = 3.4e38f;
    int bi = 0;
    #pragma unroll 1
    for (int i = 0; i < NSPAN; ++i) {
        float d = t - Kn[i + DEG];
        float m = (d > 1e-8f) ? d : 1.0f;
        if (m < best) { best = m; bi = i; }
    }
    int span = bi + DEG;
    if (span > MAXSPAN) span = MAXSPAN;   // lower clip implicit (bi >= 0)

    // _basis: Cox-de Boor, replicated term-for-term
    float Ni[DEG + 1];
    Ni[0] = 1.0f;
    #pragma unroll
    for (int k = 1; k <= DEG; ++k) {
        float saved = 0.0f;
        #pragma unroll
        for (int r = 0; r < k; ++r) {
            float K1 = Kn[span + r + 1];
            float K2 = Kn[span + 1 - k + r];
            float denom = (K1 - t) + (t - K2);
            float temp = (denom == 0.0f) ? 1e-4f : (Ni[r] / denom);
            Ni[r] = saved + (K1 - t) * temp;
            saved = (t - K2) * temp;
        }
        Ni[k] = saved;
    }
    span_out = span;
    N_out = make_float4(Ni[0], Ni[1], Ni[2], Ni[3]);
}

// Kernel A: per batch — normalize knots (cumsum), then span+basis for all
// 256 u-samples and 256 v-samples. Grid = BB, block = 256.
__global__ void prep_kernel(const float* __restrict__ knot_u,
                            const float* __restrict__ knot_v,
                            const float* __restrict__ uu,
                            const float* __restrict__ vv) {
    __shared__ float sU[KLEN];
    __shared__ float sV[KLEN];
    const int b = blockIdx.x;
    const int tid = threadIdx.x;

    // FIX (R1 bug): 2*KLEN > blockDim left sV[124..131] unwritten.
    // Each thread < KLEN now loads BOTH arrays.
    if (tid < KLEN) {
        float x = knot_u[b * KLEN + tid];
        sU[tid] = (x < 0.0f) ? 1e-4f : x;
        float y = knot_v[b * KLEN + tid];
        sV[tid] = (y < 0.0f) ? 1e-4f : y;
    }
    __syncthreads();

    // serial cumsum (132 elems) — two threads in different warps, in parallel
    if (tid == 0) {
        float s = 0.0f;
        for (int i = 0; i < KLEN; ++i) { s += sU[i]; sU[i] = s; }
    }
    if (tid == 32) {
        float s = 0.0f;
        for (int i = 0; i < KLEN; ++i) { s += sV[i]; sV[i] = s; }
    }
    __syncthreads();

    const float au = sU[0], du = sU[KLEN - 1] - au;
    const float av = sV[0], dv = sV[KLEN - 1] - av;
    __syncthreads();
    if (tid < KLEN) {
        sU[tid] = (sU[tid] - au) / du;
        sV[tid] = (sV[tid] - av) / dv;
    }
    __syncthreads();

    const int s = tid;  // one thread per sample (blockDim == SS == 256)
    int sp;
    float4 N;
    span_basis(sU, uu[s], sp, N);
    g_us[b][s] = sp;
    g_Nu[b][s] = N;
    span_basis(sV, vv[s], sp, N);
    g_vs[b][s] = sp;
    g_Nv[b][s] = N;
}

// Kernel B: one block per (b, iu). Step 1: contract over the 4 u-control rows
// into shared T[vc][d] (384 floats) — the 4 rows are CONTIGUOUS in gmem
// (1536 consecutive floats), so the loads are perfectly coalesced.
// Step 2: each thread = one v-sample: 12 LDS + 12 FMA + 3 coalesced STG.
__global__ void eval_kernel(const float* __restrict__ ctrl,
                            float* __restrict__ out) {
    __shared__ float Tsh[NCTRL * 3];   // 1.5 KB

    const int b  = blockIdx.x >> 8;
    const int iu = blockIdx.x & 255;
    const int tid = threadIdx.x;

    const float4 nu = g_Nu[b][iu];       // uniform across block
    const int    us = g_us[b][iu];

    // rows (us-3 .. us) of ctrl[b] : contiguous span of 4*128*3 = 1536 floats
    const float* base = ctrl + ((size_t)(b * NCTRL + (us - DEG)) * NCTRL) * 3;

    #pragma unroll
    for (int e = tid; e < NCTRL * 3; e += 256) {
        float t = nu.x * base[e]
                + nu.y * base[e + NCTRL * 3]
                + nu.z * base[e + 2 * NCTRL * 3]
                + nu.w * base[e + 3 * NCTRL * 3];
        Tsh[e] = t;
    }
    __syncthreads();

    const int iv   = tid;
    const float4 nv = g_Nv[b][iv];
    const int    off = (g_vs[b][iv] - DEG) * 3;

    float a0 = nv.x * Tsh[off + 0] + nv.y * Tsh[off + 3] + nv.z * Tsh[off + 6] + nv.w * Tsh[off + 9];
    float a1 = nv.x * Tsh[off + 1] + nv.y * Tsh[off + 4] + nv.z * Tsh[off + 7] + nv.w * Tsh[off + 10];
    float a2 = nv.x * Tsh[off + 2] + nv.y * Tsh[off + 5] + nv.z * Tsh[off + 8] + nv.w * Tsh[off + 11];

    const size_t o = ((size_t)blockIdx.x * SS + iv) * 3;
    out[o + 0] = a0;
    out[o + 1] = a1;
    out[o + 2] = a2;
}

extern "C" void kernel_launch(void* const* d_in, const int* in_sizes, int n_in,
                              void* d_out, int out_size) {
    const float* ctrl = (const float*)d_in[0];   // (B, 128, 128, 3)
    const float* ku   = (const float*)d_in[1];   // (B, 132)
    const float* kv   = (const float*)d_in[2];   // (B, 132)
    const float* u    = (const float*)d_in[3];   // (256)
    const float* v    = (const float*)d_in[4];   // (256)
    float* out = (float*)d_out;                  // (B, 256, 256, 3)

    prep_kernel<<<BB, 256>>>(ku, kv, u, v);
    eval_kernel<<<BB * SS, 256>>>(ctrl, out);
}

// round 9
// speedup vs baseline: 1.1065x; 1.1065x over previous
#include <cuda_runtime.h>

// Problem constants (from reference)
#define BB      16      // batch
#define SS      256     // SU == SV
#define DEG     3       // P == Q
#define KLEN    132     // M + P + 2 == N + Q + 2
#define NCTRL   128     // M+1 == N+1
#define MAXSPAN 127     // M == N
#define NSPAN   (KLEN - 2*DEG)   // 126 candidate spans
#define IUPB    4       // iu values per eval block

// Precomputed per-(b, sample): basis weights (4) and span index, for u and v.
__device__ float4 g_Nu[BB][SS];
__device__ float4 g_Nv[BB][SS];
__device__ int    g_us[BB][SS];
__device__ int    g_vs[BB][SS];

// Span search. Reference: masked = where(t-K[i+3] > 1e-8, d, 1.0), argmin
// (first occurrence). K nondecreasing -> d nonincreasing -> predicate
// (d > EPS) is true on a prefix; the min of masked is the LAST true index
// (smallest positive d), with first-occurrence ties resolved by walking back
// over equal knot values. Binary search on the exact predicate.
__device__ __forceinline__ int find_span(const float* __restrict__ Kn, float t) {
    int bi = 0;
    if (t - Kn[DEG] > 1e-8f) {
        int lo = 0, hi = NSPAN - 1;
        while (lo < hi) {
            int mid = (lo + hi + 1) >> 1;
            if (t - Kn[mid + DEG] > 1e-8f) lo = mid; else hi = mid - 1;
        }
        bi = lo;
        while (bi > 0 && Kn[bi + DEG] == Kn[bi - 1 + DEG]) --bi;  // tie -> first
    }
    int span = bi + DEG;
    return (span > MAXSPAN) ? MAXSPAN : span;
}

// Cox-de Boor basis, replicated term-for-term from the reference.
__device__ __forceinline__ float4 basis(const float* __restrict__ Kn, float t, int span) {
    float Ni[DEG + 1];
    Ni[0] = 1.0f;
    #pragma unroll
    for (int k = 1; k <= DEG; ++k) {
        float saved = 0.0f;
        #pragma unroll
        for (int r = 0; r < k; ++r) {
            float K1 = Kn[span + r + 1];
            float K2 = Kn[span + 1 - k + r];
            float denom = (K1 - t) + (t - K2);
            float temp = (denom == 0.0f) ? 1e-4f : (Ni[r] / denom);
            Ni[r] = saved + (K1 - t) * temp;
            saved = (t - K2) * temp;
        }
        Ni[k] = saved;
    }
    return make_float4(Ni[0], Ni[1], Ni[2], Ni[3]);
}

// Kernel A: per batch — normalize knots (serial cumsum, exact order), then
// span+basis for all 256 u-samples and 256 v-samples. Grid = BB, block = 256.
__global__ void prep_kernel(const float* __restrict__ knot_u,
                            const float* __restrict__ knot_v,
                            const float* __restrict__ uu,
                            const float* __restrict__ vv) {
    __shared__ float sU[KLEN];
    __shared__ float sV[KLEN];
    const int b = blockIdx.x;
    const int tid = threadIdx.x;

    if (tid < KLEN) {
        float x = knot_u[b * KLEN + tid];
        sU[tid] = (x < 0.0f) ? 1e-4f : x;
        float y = knot_v[b * KLEN + tid];
        sV[tid] = (y < 0.0f) ? 1e-4f : y;
    }
    __syncthreads();

    // serial cumsum (exact reference order) — two threads in different warps
    if (tid == 0) {
        float s = 0.0f;
        for (int i = 0; i < KLEN; ++i) { s += sU[i]; sU[i] = s; }
    }
    if (tid == 32) {
        float s = 0.0f;
        for (int i = 0; i < KLEN; ++i) { s += sV[i]; sV[i] = s; }
    }
    __syncthreads();

    const float au = sU[0], du = sU[KLEN - 1] - au;
    const float av = sV[0], dv = sV[KLEN - 1] - av;
    __syncthreads();
    if (tid < KLEN) {
        sU[tid] = (sU[tid] - au) / du;
        sV[tid] = (sV[tid] - av) / dv;
    }
    __syncthreads();

    const int s = tid;  // one thread per sample (blockDim == SS == 256)
    float tu = uu[s], tv = vv[s];
    int spu = find_span(sU, tu);
    g_us[b][s] = spu;
    g_Nu[b][s] = basis(sU, tu, spu);
    int spv = find_span(sV, tv);
    g_vs[b][s] = spv;
    g_Nv[b][s] = basis(sV, tv, spv);
}

// Kernel B: one block per (b, 4 consecutive iu). Phase 1: for each of the 4
// iu, contract the 4 u-control rows into shared T[buf][128*3] using float4
// loads (rows are 16B-aligned, 96 float4 apart). 384 float4-tasks over 256
// threads, each task = 4x LDG.128 + 12 FMA + 1x STS.128. Phase 2: each
// thread = one v-sample x 4 iu, with nv/voff cached in registers.
__global__ void eval_kernel(const float* __restrict__ ctrl,
                            float* __restrict__ out) {
    __shared__ float4 Tsh[IUPB][NCTRL * 3 / 4];   // 4 x 1.5 KB

    const int b   = blockIdx.x / (SS / IUPB);
    const int iu0 = (blockIdx.x % (SS / IUPB)) * IUPB;
    const int tid = threadIdx.x;

    // per-thread v data (reused for all 4 iu) — issued before the LDG storm
    const float4 nv  = g_Nv[b][tid];
    const int  voff  = (g_vs[b][tid] - DEG) * 3;

    #pragma unroll
    for (int L = tid; L < IUPB * 96; L += 256) {
        const int buf = L / 96;
        const int f   = L % 96;
        const float4 nu = g_Nu[b][iu0 + buf];
        const int    us = g_us[b][iu0 + buf];
        const float4* base = (const float4*)(ctrl +
            ((size_t)(b * NCTRL + (us - DEG)) * NCTRL) * 3);
        float4 r0 = base[f];
        float4 r1 = base[f + 96];
        float4 r2 = base[f + 192];
        float4 r3 = base[f + 288];
        float4 t;
        t.x = nu.x * r0.x + nu.y * r1.x + nu.z * r2.x + nu.w * r3.x;
        t.y = nu.x * r0.y + nu.y * r1.y + nu.z * r2.y + nu.w * r3.y;
        t.z = nu.x * r0.z + nu.y * r1.z + nu.z * r2.z + nu.w * r3.z;
        t.w = nu.x * r0.w + nu.y * r1.w + nu.z * r2.w + nu.w * r3.w;
        Tsh[buf][f] = t;
    }
    __syncthreads();

    #pragma unroll
    for (int buf = 0; buf < IUPB; ++buf) {
        const float* T = (const float*)Tsh[buf];
        float a0 = nv.x * T[voff + 0] + nv.y * T[voff + 3] + nv.z * T[voff + 6] + nv.w * T[voff + 9];
        float a1 = nv.x * T[voff + 1] + nv.y * T[voff + 4] + nv.z * T[voff + 7] + nv.w * T[voff + 10];
        float a2 = nv.x * T[voff + 2] + nv.y * T[voff + 5] + nv.z * T[voff + 8] + nv.w * T[voff + 11];
        const size_t o = (((size_t)b * SS + (iu0 + buf)) * SS + tid) * 3;
        out[o + 0] = a0;
        out[o + 1] = a1;
        out[o + 2] = a2;
    }
}

extern "C" void kernel_launch(void* const* d_in, const int* in_sizes, int n_in,
                              void* d_out, int out_size) {
    const float* ctrl = (const float*)d_in[0];   // (B, 128, 128, 3)
    const float* ku   = (const float*)d_in[1];   // (B, 132)
    const float* kv   = (const float*)d_in[2];   // (B, 132)
    const float* u    = (const float*)d_in[3];   // (256)
    const float* v    = (const float*)d_in[4];   // (256)
    float* out = (float*)d_out;                  // (B, 256, 256, 3)

    prep_kernel<<<BB, 256>>>(ku, kv, u, v);
    eval_kernel<<<BB * SS / IUPB, 256>>>(ctrl, out);
}

// round 10
// speedup vs baseline: 1.5435x; 1.3949x over previous
#include <cuda_runtime.h>

// Problem constants (from reference)
#define BB      16      // batch
#define SS      256     // SU == SV
#define DEG     3       // P == Q
#define KLEN    132     // M + P + 2 == N + Q + 2
#define NCTRL   128     // M+1 == N+1
#define MAXSPAN 127     // M == N
#define NSPAN   (KLEN - 2*DEG)   // 126 candidate spans
#define IUPB    4       // iu values per eval block
#define TPB     128     // eval block size

// Precomputed per-(b, sample): basis weights (4) and span index, for u and v.
__device__ float4 g_Nu[BB][SS];
__device__ float4 g_Nv[BB][SS];
__device__ int    g_us[BB][SS];
__device__ int    g_vs[BB][SS];

// Span search. Reference: masked = where(t-K[i+3] > 1e-8, d, 1.0), argmin
// (first occurrence). K nondecreasing -> predicate true on a prefix; min of
// masked = LAST true index, ties walk back to first equal knot.
__device__ __forceinline__ int find_span(const float* __restrict__ Kn, float t) {
    int bi = 0;
    if (t - Kn[DEG] > 1e-8f) {
        int lo = 0, hi = NSPAN - 1;
        while (lo < hi) {
            int mid = (lo + hi + 1) >> 1;
            if (t - Kn[mid + DEG] > 1e-8f) lo = mid; else hi = mid - 1;
        }
        bi = lo;
        while (bi > 0 && Kn[bi + DEG] == Kn[bi - 1 + DEG]) --bi;  // tie -> first
    }
    int span = bi + DEG;
    return (span > MAXSPAN) ? MAXSPAN : span;
}

// Cox-de Boor basis, replicated term-for-term from the reference.
__device__ __forceinline__ float4 basis(const float* __restrict__ Kn, float t, int span) {
    float Ni[DEG + 1];
    Ni[0] = 1.0f;
    #pragma unroll
    for (int k = 1; k <= DEG; ++k) {
        float saved = 0.0f;
        #pragma unroll
        for (int r = 0; r < k; ++r) {
            float K1 = Kn[span + r + 1];
            float K2 = Kn[span + 1 - k + r];
            float denom = (K1 - t) + (t - K2);
            float temp = (denom == 0.0f) ? 1e-4f : (Ni[r] / denom);
            Ni[r] = saved + (K1 - t) * temp;
            saved = (t - K2) * temp;
        }
        Ni[k] = saved;
    }
    return make_float4(Ni[0], Ni[1], Ni[2], Ni[3]);
}

// Kernel A: per batch — normalize knots (serial cumsum, exact order), then
// span+basis for all 256 u-samples and 256 v-samples. Grid = BB, block = 256.
__global__ void prep_kernel(const float* __restrict__ knot_u,
                            const float* __restrict__ knot_v,
                            const float* __restrict__ uu,
                            const float* __restrict__ vv) {
    __shared__ float sU[KLEN];
    __shared__ float sV[KLEN];
    const int b = blockIdx.x;
    const int tid = threadIdx.x;

    if (tid < KLEN) {
        float x = knot_u[b * KLEN + tid];
        sU[tid] = (x < 0.0f) ? 1e-4f : x;
        float y = knot_v[b * KLEN + tid];
        sV[tid] = (y < 0.0f) ? 1e-4f : y;
    }
    __syncthreads();

    if (tid == 0) {
        float s = 0.0f;
        for (int i = 0; i < KLEN; ++i) { s += sU[i]; sU[i] = s; }
    }
    if (tid == 32) {
        float s = 0.0f;
        for (int i = 0; i < KLEN; ++i) { s += sV[i]; sV[i] = s; }
    }
    __syncthreads();

    const float au = sU[0], du = sU[KLEN - 1] - au;
    const float av = sV[0], dv = sV[KLEN - 1] - av;
    __syncthreads();
    if (tid < KLEN) {
        sU[tid] = (sU[tid] - au) / du;
        sV[tid] = (sV[tid] - av) / dv;
    }
    __syncthreads();

    const int s = tid;
    float tu = uu[s], tv = vv[s];
    int spu = find_span(sU, tu);
    g_us[b][s] = spu;
    g_Nu[b][s] = basis(sU, tu, spu);
    int spv = find_span(sV, tv);
    g_vs[b][s] = spv;
    g_Nv[b][s] = basis(sV, tv, spv);
}

// Kernel B: block = 128 threads, 4 iu per block, grid = 2048.
// Phase 1 (balanced: exactly 3 tasks/thread): contract 4 u-rows into shared
// T, stored PADDED as 4 floats per v-ctrl point (x,y,z,pad) so phase 2 can
// use LDS.128. Phase 2: each thread = 2 v-samples x 4 iu; per output:
// 4x LDS.128 + 12 FMA + 3 coalesced STG.
__global__ void eval_kernel(const float* __restrict__ ctrl,
                            float* __restrict__ out) {
    __shared__ __align__(16) float Tsh[IUPB][NCTRL * 4];   // 4 x 2 KB padded

    const int b   = blockIdx.x / (SS / IUPB);
    const int iu0 = (blockIdx.x % (SS / IUPB)) * IUPB;
    const int tid = threadIdx.x;

    // per-thread v data for the 2 samples this thread evaluates (issued early)
    const int v0 = tid, v1 = tid + TPB;
    const float4 nva = g_Nv[b][v0];
    const float4 nvb = g_Nv[b][v1];
    const int    vca = g_vs[b][v0] - DEG;
    const int    vcb = g_vs[b][v1] - DEG;

    #pragma unroll
    for (int L = tid; L < IUPB * 96; L += TPB) {   // 3 balanced iterations
        const int buf = L / 96;
        const int f   = L % 96;
        const float4 nu = g_Nu[b][iu0 + buf];
        const int    us = g_us[b][iu0 + buf];
        const float4* base = (const float4*)(ctrl +
            ((size_t)(b * NCTRL + (us - DEG)) * NCTRL) * 3);
        float4 r0 = base[f];
        float4 r1 = base[f + 96];
        float4 r2 = base[f + 192];
        float4 r3 = base[f + 288];
        float t[4];
        t[0] = nu.x * r0.x + nu.y * r1.x + nu.z * r2.x + nu.w * r3.x;
        t[1] = nu.x * r0.y + nu.y * r1.y + nu.z * r2.y + nu.w * r3.y;
        t[2] = nu.x * r0.z + nu.y * r1.z + nu.z * r2.z + nu.w * r3.z;
        t[3] = nu.x * r0.w + nu.y * r1.w + nu.z * r2.w + nu.w * r3.w;
        const int e0 = 4 * f;
        #pragma unroll
        for (int i = 0; i < 4; ++i) {
            const int j  = e0 + i;
            const int vc = j / 3;
            Tsh[buf][vc * 4 + (j - vc * 3)] = t[i];   // padded scatter
        }
    }
    __syncthreads();

    #pragma unroll
    for (int buf = 0; buf < IUPB; ++buf) {
        const float4* Tb = (const float4*)Tsh[buf];
        // v-sample v0
        {
            float4 q0 = Tb[vca], q1 = Tb[vca + 1], q2 = Tb[vca + 2], q3 = Tb[vca + 3];
            float a0 = nva.x * q0.x + nva.y * q1.x + nva.z * q2.x + nva.w * q3.x;
            float a1 = nva.x * q0.y + nva.y * q1.y + nva.z * q2.y + nva.w * q3.y;
            float a2 = nva.x * q0.z + nva.y * q1.z + nva.z * q2.z + nva.w * q3.z;
            const size_t o = (((size_t)b * SS + (iu0 + buf)) * SS + v0) * 3;
            out[o + 0] = a0; out[o + 1] = a1; out[o + 2] = a2;
        }
        // v-sample v1
        {
            float4 q0 = Tb[vcb], q1 = Tb[vcb + 1], q2 = Tb[vcb + 2], q3 = Tb[vcb + 3];
            float a0 = nvb.x * q0.x + nvb.y * q1.x + nvb.z * q2.x + nvb.w * q3.x;
            float a1 = nvb.x * q0.y + nvb.y * q1.y + nvb.z * q2.y + nvb.w * q3.y;
            float a2 = nvb.x * q0.z + nvb.y * q1.z + nvb.z * q2.z + nvb.w * q3.z;
            const size_t o = (((size_t)b * SS + (iu0 + buf)) * SS + v1) * 3;
            out[o + 0] = a0; out[o + 1] = a1; out[o + 2] = a2;
        }
    }
}

extern "C" void kernel_launch(void* const* d_in, const int* in_sizes, int n_in,
                              void* d_out, int out_size) {
    const float* ctrl = (const float*)d_in[0];   // (B, 128, 128, 3)
    const float* ku   = (const float*)d_in[1];   // (B, 132)
    const float* kv   = (const float*)d_in[2];   // (B, 132)
    const float* u    = (const float*)d_in[3];   // (256)
    const float* v    = (const float*)d_in[4];   // (256)
    float* out = (float*)d_out;                  // (B, 256, 256, 3)

    prep_kernel<<<BB, 256>>>(ku, kv, u, v);
    eval_kernel<<<BB * SS / IUPB, TPB>>>(ctrl, out);
}